// round 1
// baseline (speedup 1.0000x reference)
#include <cuda_runtime.h>

#define B_  8
#define N_  1024
#define C_  768
#define H_  12
#define D_  64
#define BH_ (B_*H_)     // 96
#define M_  (B_*N_)     // 8192
#define TC_ (3*C_)      // 2304

// Scratch (device globals: allocation-free rule)
__device__ float g_QKV[(size_t)M_ * TC_];      // [B*N, 3C]
__device__ float g_Q  [(size_t)BH_ * N_ * D_]; // [B*H, N, D] normalized*scale
__device__ float g_K  [(size_t)BH_ * N_ * D_]; // [B*H, N, D] normalized
__device__ float g_AO [(size_t)M_ * C_];       // [B*N, C] attention output

// ---------------------------------------------------------------------------
// Generic SGEMM: C[M,N] = A[M,K] @ W[N,K]^T (+bias). 64x64 tile, BK=16,
// 256 threads, 4x4 micro-tile per thread. All dims divide evenly -> no guards.
// ---------------------------------------------------------------------------
__global__ void __launch_bounds__(256) sgemm_nt(
    const float* __restrict__ A, const float* __restrict__ W,
    const float* __restrict__ bias, float* __restrict__ C,
    int N, int K)
{
    __shared__ float As[16][64];
    __shared__ float Bs[16][64];

    const int n0 = blockIdx.x * 64;
    const int m0 = blockIdx.y * 64;
    const int tid = threadIdx.x;
    const int tx = tid & 15;         // 0..15 (cols)
    const int ty = tid >> 4;         // 0..15 (rows)
    const int lm = tid >> 2;         // 0..63 load row
    const int lk = (tid & 3) << 2;   // 0,4,8,12 load k base

    const float* Ag = A + (size_t)(m0 + lm) * K + lk;
    const float* Wg = W + (size_t)(n0 + lm) * K + lk;

    float acc[4][4] = {};

    for (int k0 = 0; k0 < K; k0 += 16) {
        const float4 av = *(const float4*)(Ag + k0);
        const float4 wv = *(const float4*)(Wg + k0);
        __syncthreads();
        As[lk+0][lm] = av.x; As[lk+1][lm] = av.y; As[lk+2][lm] = av.z; As[lk+3][lm] = av.w;
        Bs[lk+0][lm] = wv.x; Bs[lk+1][lm] = wv.y; Bs[lk+2][lm] = wv.z; Bs[lk+3][lm] = wv.w;
        __syncthreads();
        #pragma unroll
        for (int k = 0; k < 16; ++k) {
            const float4 a = *(const float4*)&As[k][ty << 2];
            const float4 b = *(const float4*)&Bs[k][tx << 2];
            const float ar[4] = {a.x, a.y, a.z, a.w};
            const float br[4] = {b.x, b.y, b.z, b.w};
            #pragma unroll
            for (int i = 0; i < 4; ++i)
                #pragma unroll
                for (int j = 0; j < 4; ++j)
                    acc[i][j] = fmaf(ar[i], br[j], acc[i][j]);
        }
    }

    #pragma unroll
    for (int i = 0; i < 4; ++i) {
        float4 r;
        r.x = acc[i][0]; r.y = acc[i][1]; r.z = acc[i][2]; r.w = acc[i][3];
        if (bias) {
            const float4 bv = *(const float4*)(bias + n0 + (tx << 2));
            r.x += bv.x; r.y += bv.y; r.z += bv.z; r.w += bv.w;
        }
        *(float4*)(C + (size_t)(m0 + (ty << 2) + i) * N + n0 + (tx << 2)) = r;
    }
}

// ---------------------------------------------------------------------------
// Per-head q/k standardization (torch unbiased std, ddof=1), one warp per row
// of 64. Writes Q (scaled by D^-0.5) and K into [B*H, N, D] layout.
// ---------------------------------------------------------------------------
__global__ void __launch_bounds__(256) norm_qk_kernel(const float* __restrict__ qkv)
{
    const int warp = threadIdx.x >> 5;
    const int lane = threadIdx.x & 31;
    const int row  = blockIdx.x * 8 + warp;      // 0 .. 2*BH_*N_-1
    const int isK  = row >= BH_ * N_;
    const int rid  = isK ? row - BH_ * N_ : row; // bh*1024 + n
    const int bh = rid >> 10;
    const int n  = rid & 1023;
    const int b = bh / H_, h = bh % H_;

    const float* src = qkv + ((size_t)(b * N_ + n)) * TC_ + (isK ? C_ : 0) + h * D_;
    const float2 v = ((const float2*)src)[lane];

    float s  = v.x + v.y;
    float ss = v.x * v.x + v.y * v.y;
    #pragma unroll
    for (int off = 16; off; off >>= 1) {
        s  += __shfl_xor_sync(0xffffffffu, s,  off);
        ss += __shfl_xor_sync(0xffffffffu, ss, off);
    }
    const float mean = s * (1.0f / 64.0f);
    const float var  = (ss - 64.0f * mean * mean) * (1.0f / 63.0f);
    const float rs   = rsqrtf(var);
    const float sc   = isK ? rs : rs * 0.125f;   // fold SCALE = D^-0.5 into Q

    float2 o;
    o.x = (v.x - mean) * sc;
    o.y = (v.y - mean) * sc;
    float* dst = (isK ? g_K : g_Q) + (size_t)rid * 64;
    ((float2*)dst)[lane] = o;
}

// ---------------------------------------------------------------------------
// Flash-style attention per (b,h): 64 q-rows per block, stream keys in tiles
// of 32, online softmax. 256 threads; thread owns 2 q-rows x (4 S cols / 8 O
// cols). Writes output directly in [B,N,C] layout for the proj GEMM.
// ---------------------------------------------------------------------------
#define ST 68   // smem row stride (floats): 16B-aligned, conflict-free patterns

__global__ void __launch_bounds__(256) attn_kernel(
    const float* __restrict__ qkv, float* __restrict__ AO)
{
    __shared__ float Qs[64 * ST];
    __shared__ float Ks[32 * ST];
    __shared__ float Vs[32 * ST];
    __shared__ float Ps[64 * 36];

    const int bh = blockIdx.y;
    const int n0 = blockIdx.x << 6;
    const int b = bh / H_, h = bh % H_;
    const int tid = threadIdx.x;

    const float* Qg = g_Q + ((size_t)bh * N_ + n0) * 64;
    for (int i = tid; i < 64 * 64; i += 256)
        Qs[(i >> 6) * ST + (i & 63)] = Qg[i];

    const int r0 = (tid >> 3) << 1;   // even row 0..62 (2 rows per thread)
    const int g  = tid & 7;           // S col group / O col group

    const float* Kg = g_K + (size_t)bh * N_ * 64;
    const float* Vg = qkv + (size_t)b * N_ * TC_ + 2 * C_ + h * D_;

    float o[2][8] = {};
    float m0v = -1e30f, m1v = -1e30f, l0 = 0.0f, l1 = 0.0f;

    for (int t = 0; t < 32; ++t) {
        __syncthreads();
        for (int i = tid; i < 32 * 64; i += 256) {
            const int kk = i >> 6, d = i & 63;
            Ks[kk * ST + d] = Kg[(size_t)(t * 32 + kk) * 64 + d];
            Vs[kk * ST + d] = Vg[(size_t)(t * 32 + kk) * TC_ + d];
        }
        __syncthreads();

        // S = Q Ktile^T : thread computes rows {r0,r0+1} x cols {g+8j}
        float s0[4] = {}, s1[4] = {};
        #pragma unroll
        for (int d4 = 0; d4 < 64; d4 += 4) {
            const float4 a0 = *(const float4*)&Qs[r0 * ST + d4];
            const float4 a1 = *(const float4*)&Qs[(r0 + 1) * ST + d4];
            #pragma unroll
            for (int j = 0; j < 4; ++j) {
                const float4 bk = *(const float4*)&Ks[(g + 8 * j) * ST + d4];
                s0[j] = fmaf(a0.x, bk.x, s0[j]); s0[j] = fmaf(a0.y, bk.y, s0[j]);
                s0[j] = fmaf(a0.z, bk.z, s0[j]); s0[j] = fmaf(a0.w, bk.w, s0[j]);
                s1[j] = fmaf(a1.x, bk.x, s1[j]); s1[j] = fmaf(a1.y, bk.y, s1[j]);
                s1[j] = fmaf(a1.z, bk.z, s1[j]); s1[j] = fmaf(a1.w, bk.w, s1[j]);
            }
        }

        // online softmax (8 threads per row; lanes g=0..7 contiguous -> shfl)
        {
            float mt = fmaxf(fmaxf(s0[0], s0[1]), fmaxf(s0[2], s0[3]));
            mt = fmaxf(mt, __shfl_xor_sync(0xffffffffu, mt, 1));
            mt = fmaxf(mt, __shfl_xor_sync(0xffffffffu, mt, 2));
            mt = fmaxf(mt, __shfl_xor_sync(0xffffffffu, mt, 4));
            const float mn = fmaxf(m0v, mt);
            const float cr = __expf(m0v - mn);
            float ps = 0.0f;
            #pragma unroll
            for (int j = 0; j < 4; ++j) {
                const float p = __expf(s0[j] - mn);
                Ps[r0 * 36 + g + 8 * j] = p;
                ps += p;
            }
            ps += __shfl_xor_sync(0xffffffffu, ps, 1);
            ps += __shfl_xor_sync(0xffffffffu, ps, 2);
            ps += __shfl_xor_sync(0xffffffffu, ps, 4);
            l0 = l0 * cr + ps; m0v = mn;
            #pragma unroll
            for (int j = 0; j < 8; ++j) o[0][j] *= cr;
        }
        {
            float mt = fmaxf(fmaxf(s1[0], s1[1]), fmaxf(s1[2], s1[3]));
            mt = fmaxf(mt, __shfl_xor_sync(0xffffffffu, mt, 1));
            mt = fmaxf(mt, __shfl_xor_sync(0xffffffffu, mt, 2));
            mt = fmaxf(mt, __shfl_xor_sync(0xffffffffu, mt, 4));
            const float mn = fmaxf(m1v, mt);
            const float cr = __expf(m1v - mn);
            float ps = 0.0f;
            #pragma unroll
            for (int j = 0; j < 4; ++j) {
                const float p = __expf(s1[j] - mn);
                Ps[(r0 + 1) * 36 + g + 8 * j] = p;
                ps += p;
            }
            ps += __shfl_xor_sync(0xffffffffu, ps, 1);
            ps += __shfl_xor_sync(0xffffffffu, ps, 2);
            ps += __shfl_xor_sync(0xffffffffu, ps, 4);
            l1 = l1 * cr + ps; m1v = mn;
            #pragma unroll
            for (int j = 0; j < 8; ++j) o[1][j] *= cr;
        }
        __syncwarp();

        // O += P @ Vtile : thread owns rows {r0,r0+1} x cols g*8..g*8+7
        #pragma unroll
        for (int k = 0; k < 32; ++k) {
            const float p0 = Ps[r0 * 36 + k];
            const float p1 = Ps[(r0 + 1) * 36 + k];
            const float4 v0 = *(const float4*)&Vs[k * ST + (g << 3)];
            const float4 v1 = *(const float4*)&Vs[k * ST + (g << 3) + 4];
            o[0][0] = fmaf(p0, v0.x, o[0][0]); o[0][1] = fmaf(p0, v0.y, o[0][1]);
            o[0][2] = fmaf(p0, v0.z, o[0][2]); o[0][3] = fmaf(p0, v0.w, o[0][3]);
            o[0][4] = fmaf(p0, v1.x, o[0][4]); o[0][5] = fmaf(p0, v1.y, o[0][5]);
            o[0][6] = fmaf(p0, v1.z, o[0][6]); o[0][7] = fmaf(p0, v1.w, o[0][7]);
            o[1][0] = fmaf(p1, v0.x, o[1][0]); o[1][1] = fmaf(p1, v0.y, o[1][1]);
            o[1][2] = fmaf(p1, v0.z, o[1][2]); o[1][3] = fmaf(p1, v0.w, o[1][3]);
            o[1][4] = fmaf(p1, v1.x, o[1][4]); o[1][5] = fmaf(p1, v1.y, o[1][5]);
            o[1][6] = fmaf(p1, v1.z, o[1][6]); o[1][7] = fmaf(p1, v1.w, o[1][7]);
        }
        __syncwarp();
    }

    const float il0 = 1.0f / l0;
    const float il1 = 1.0f / l1;
    float* dst0 = AO + ((size_t)(b * N_ + n0 + r0)) * C_ + h * D_ + (g << 3);
    float* dst1 = dst0 + C_;
    float4 w;
    w.x = o[0][0]*il0; w.y = o[0][1]*il0; w.z = o[0][2]*il0; w.w = o[0][3]*il0;
    *(float4*)dst0 = w;
    w.x = o[0][4]*il0; w.y = o[0][5]*il0; w.z = o[0][6]*il0; w.w = o[0][7]*il0;
    *(float4*)(dst0 + 4) = w;
    w.x = o[1][0]*il1; w.y = o[1][1]*il1; w.z = o[1][2]*il1; w.w = o[1][3]*il1;
    *(float4*)dst1 = w;
    w.x = o[1][4]*il1; w.y = o[1][5]*il1; w.z = o[1][6]*il1; w.w = o[1][7]*il1;
    *(float4*)(dst1 + 4) = w;
}

// ---------------------------------------------------------------------------
extern "C" void kernel_launch(void* const* d_in, const int* in_sizes, int n_in,
                              void* d_out, int out_size)
{
    const float* x      = (const float*)d_in[0];   // [8,1024,768]
    const float* qkv_w  = (const float*)d_in[1];   // [2304,768]
    const float* proj_w = (const float*)d_in[2];   // [768,768]
    const float* proj_b = (const float*)d_in[3];   // [768]
    float* out = (float*)d_out;                    // [8,1024,768] fp32

    float *qkv, *ao;
    cudaGetSymbolAddress((void**)&qkv, g_QKV);
    cudaGetSymbolAddress((void**)&ao,  g_AO);

    // 1) QKV projection: [8192,2304] = x @ qkv_w^T
    sgemm_nt<<<dim3(TC_ / 64, M_ / 64), 256>>>(x, qkv_w, nullptr, qkv, TC_, C_);
    // 2) per-head q/k standardization (+ fold in softmax scale)
    norm_qk_kernel<<<(2 * BH_ * N_) / 8, 256>>>(qkv);
    // 3) flash attention per (b,h), output in [B,N,C]
    attn_kernel<<<dim3(N_ / 64, BH_), 256>>>(qkv, ao);
    // 4) output projection + bias
    sgemm_nt<<<dim3(C_ / 64, M_ / 64), 256>>>(ao, proj_w, proj_b, out, C_, C_);
}

// round 2
// speedup vs baseline: 3.5705x; 3.5705x over previous
#include <cuda_runtime.h>

#define B_  8
#define N_  1024
#define C_  768
#define H_  12
#define D_  64
#define BH_ (B_*H_)     // 96
#define M_  (B_*N_)     // 8192
#define TC_ (3*C_)      // 2304

// Scratch (device globals: allocation-free rule)
__device__ float g_QKV[(size_t)M_ * TC_];      // [B*N, 3C]
__device__ float g_Q  [(size_t)BH_ * N_ * D_]; // [B*H, N, D] normalized*scale
__device__ float g_K  [(size_t)BH_ * N_ * D_]; // [B*H, N, D] normalized
__device__ float g_AO [(size_t)M_ * C_];       // [B*N, C] attention output

__device__ __forceinline__ unsigned f2tf(float x) {
    unsigned r; asm("cvt.rna.tf32.f32 %0, %1;" : "=r"(r) : "f"(x)); return r;
}

// D += A(16x8,row) * B(8x8,col) in tf32, fp32 accum
__device__ __forceinline__ void mma_tf32(float* d, const unsigned* a, const unsigned* b) {
    asm volatile("mma.sync.aligned.m16n8k8.row.col.f32.tf32.tf32.f32 "
                 "{%0,%1,%2,%3}, {%4,%5,%6,%7}, {%8,%9}, {%0,%1,%2,%3};"
                 : "+f"(d[0]), "+f"(d[1]), "+f"(d[2]), "+f"(d[3])
                 : "r"(a[0]), "r"(a[1]), "r"(a[2]), "r"(a[3]),
                   "r"(b[0]), "r"(b[1]));
}

// ---------------------------------------------------------------------------
// tf32 tensor-core GEMM: C[M,N] = A[M,K] @ W[N,K]^T (+bias)
// 128x128 block tile, BK=16 double-buffered, 8 warps (4m x 2n),
// warp tile 32x64 = 2x8 m16n8k8 tiles.
// ---------------------------------------------------------------------------
__global__ void __launch_bounds__(256) gemm_tf32(
    const float* __restrict__ A, const float* __restrict__ W,
    const float* __restrict__ bias, float* __restrict__ C,
    int N, int K)
{
    __shared__ unsigned As[2][128 * 20];   // [row][k], stride 20 -> conflict-free frags
    __shared__ unsigned Ws[2][128 * 20];   // [n][k]

    const int tid  = threadIdx.x;
    const int wid  = tid >> 5, lane = tid & 31;
    const int lr   = lane >> 2, lc = lane & 3;
    const int wm   = (wid >> 1) * 32;
    const int wn   = (wid & 1) * 64;
    const int m0   = blockIdx.y * 128, n0 = blockIdx.x * 128;
    const int lrow = tid >> 2;             // 0..63
    const int lkq  = (tid & 3) * 4;        // 0,4,8,12

    const float* Ag = A + (size_t)(m0 + lrow) * K + lkq;
    const float* Wg = W + (size_t)(n0 + lrow) * K + lkq;
    const int KT = K / 16;

    float acc[2][8][4] = {};

    // prologue: tile 0 -> buffer 0
    {
        float4 a0 = *(const float4*)Ag;
        float4 a1 = *(const float4*)(Ag + (size_t)64 * K);
        float4 w0 = *(const float4*)Wg;
        float4 w1 = *(const float4*)(Wg + (size_t)64 * K);
        unsigned* Ad = As[0] + lrow * 20 + lkq;
        unsigned* Wd = Ws[0] + lrow * 20 + lkq;
        Ad[0]=f2tf(a0.x); Ad[1]=f2tf(a0.y); Ad[2]=f2tf(a0.z); Ad[3]=f2tf(a0.w);
        Ad[64*20+0]=f2tf(a1.x); Ad[64*20+1]=f2tf(a1.y); Ad[64*20+2]=f2tf(a1.z); Ad[64*20+3]=f2tf(a1.w);
        Wd[0]=f2tf(w0.x); Wd[1]=f2tf(w0.y); Wd[2]=f2tf(w0.z); Wd[3]=f2tf(w0.w);
        Wd[64*20+0]=f2tf(w1.x); Wd[64*20+1]=f2tf(w1.y); Wd[64*20+2]=f2tf(w1.z); Wd[64*20+3]=f2tf(w1.w);
    }
    __syncthreads();

    for (int kt = 0; kt < KT; ++kt) {
        float4 a0n, a1n, w0n, w1n;
        const bool pf = (kt + 1 < KT);
        if (pf) {
            const int ko = (kt + 1) * 16;
            a0n = *(const float4*)(Ag + ko);
            a1n = *(const float4*)(Ag + (size_t)64 * K + ko);
            w0n = *(const float4*)(Wg + ko);
            w1n = *(const float4*)(Wg + (size_t)64 * K + ko);
        }
        const unsigned* Ab = As[kt & 1];
        const unsigned* Wb = Ws[kt & 1];
        #pragma unroll
        for (int ks = 0; ks < 2; ++ks) {
            const int kb = ks * 8;
            unsigned af[2][4], bf[8][2];
            #pragma unroll
            for (int mt = 0; mt < 2; ++mt) {
                const int r = wm + mt * 16 + lr;
                af[mt][0] = Ab[r * 20 + kb + lc];
                af[mt][1] = Ab[(r + 8) * 20 + kb + lc];
                af[mt][2] = Ab[r * 20 + kb + lc + 4];
                af[mt][3] = Ab[(r + 8) * 20 + kb + lc + 4];
            }
            #pragma unroll
            for (int nt = 0; nt < 8; ++nt) {
                const int n = wn + nt * 8 + lr;
                bf[nt][0] = Wb[n * 20 + kb + lc];
                bf[nt][1] = Wb[n * 20 + kb + lc + 4];
            }
            #pragma unroll
            for (int mt = 0; mt < 2; ++mt)
                #pragma unroll
                for (int nt = 0; nt < 8; ++nt)
                    mma_tf32(acc[mt][nt], af[mt], bf[nt]);
        }
        if (pf) {
            unsigned* Ad = As[(kt + 1) & 1] + lrow * 20 + lkq;
            unsigned* Wd = Ws[(kt + 1) & 1] + lrow * 20 + lkq;
            Ad[0]=f2tf(a0n.x); Ad[1]=f2tf(a0n.y); Ad[2]=f2tf(a0n.z); Ad[3]=f2tf(a0n.w);
            Ad[64*20+0]=f2tf(a1n.x); Ad[64*20+1]=f2tf(a1n.y); Ad[64*20+2]=f2tf(a1n.z); Ad[64*20+3]=f2tf(a1n.w);
            Wd[0]=f2tf(w0n.x); Wd[1]=f2tf(w0n.y); Wd[2]=f2tf(w0n.z); Wd[3]=f2tf(w0n.w);
            Wd[64*20+0]=f2tf(w1n.x); Wd[64*20+1]=f2tf(w1n.y); Wd[64*20+2]=f2tf(w1n.z); Wd[64*20+3]=f2tf(w1n.w);
        }
        __syncthreads();
    }

    #pragma unroll
    for (int mt = 0; mt < 2; ++mt)
        #pragma unroll
        for (int nt = 0; nt < 8; ++nt) {
            const int col = n0 + wn + nt * 8 + 2 * lc;
            float bx = 0.f, by = 0.f;
            if (bias) { bx = bias[col]; by = bias[col + 1]; }
            const int r0 = m0 + wm + mt * 16 + lr;
            float2 v0, v1;
            v0.x = acc[mt][nt][0] + bx; v0.y = acc[mt][nt][1] + by;
            v1.x = acc[mt][nt][2] + bx; v1.y = acc[mt][nt][3] + by;
            *(float2*)&C[(size_t)r0 * N + col] = v0;
            *(float2*)&C[(size_t)(r0 + 8) * N + col] = v1;
        }
}

// ---------------------------------------------------------------------------
// Per-head q/k standardization (ddof=1), one warp per row of 64.
// ---------------------------------------------------------------------------
__global__ void __launch_bounds__(256) norm_qk_kernel(const float* __restrict__ qkv)
{
    const int warp = threadIdx.x >> 5;
    const int lane = threadIdx.x & 31;
    const int row  = blockIdx.x * 8 + warp;
    const int isK  = row >= BH_ * N_;
    const int rid  = isK ? row - BH_ * N_ : row;
    const int bh = rid >> 10;
    const int n  = rid & 1023;
    const int b = bh / H_, h = bh % H_;

    const float* src = qkv + ((size_t)(b * N_ + n)) * TC_ + (isK ? C_ : 0) + h * D_;
    const float2 v = ((const float2*)src)[lane];

    float s  = v.x + v.y;
    float ss = v.x * v.x + v.y * v.y;
    #pragma unroll
    for (int off = 16; off; off >>= 1) {
        s  += __shfl_xor_sync(0xffffffffu, s,  off);
        ss += __shfl_xor_sync(0xffffffffu, ss, off);
    }
    const float mean = s * (1.0f / 64.0f);
    const float var  = (ss - 64.0f * mean * mean) * (1.0f / 63.0f);
    const float rs   = rsqrtf(var);
    const float sc   = isK ? rs : rs * 0.125f;   // fold SCALE into Q

    float2 o;
    o.x = (v.x - mean) * sc;
    o.y = (v.y - mean) * sc;
    float* dst = (isK ? g_K : g_Q) + (size_t)rid * 64;
    ((float2*)dst)[lane] = o;
}

// ---------------------------------------------------------------------------
// Flash attention, tensor cores. Block = 128 q-rows of one (b,h).
// 8 warps; warp owns 16 q-rows (all softmax reductions warp-local).
// Keys streamed in tiles of 64. S and P@V via m16n8k8 tf32 mma.
// P fragments built from S accumulators via shuffles (no smem round-trip).
// ---------------------------------------------------------------------------
__global__ void __launch_bounds__(256) attn_tf32(
    const float* __restrict__ qkv, float* __restrict__ AO)
{
    __shared__ unsigned Ks[64 * 68];   // [key][d], stride 68
    __shared__ unsigned Vs[64 * 72];   // [key][d], stride 72

    const int tid  = threadIdx.x;
    const int wid  = tid >> 5, lane = tid & 31;
    const int lr   = lane >> 2, lc = lane & 3;
    const int qh   = (lane & ~3) + (lc >> 1);   // shuffle source base
    const int bh   = blockIdx.y;
    const int n0   = blockIdx.x * 128;
    const int b = bh / H_, h = bh % H_;

    // Q fragments (rows wid*16 + lr / +8), tf32
    unsigned qf[8][4];
    {
        const float* Qg = g_Q + ((size_t)bh * N_ + n0 + wid * 16) * 64;
        #pragma unroll
        for (int ks = 0; ks < 8; ++ks) {
            qf[ks][0] = f2tf(Qg[lr * 64 + ks * 8 + lc]);
            qf[ks][1] = f2tf(Qg[(lr + 8) * 64 + ks * 8 + lc]);
            qf[ks][2] = f2tf(Qg[lr * 64 + ks * 8 + lc + 4]);
            qf[ks][3] = f2tf(Qg[(lr + 8) * 64 + ks * 8 + lc + 4]);
        }
    }

    float o[8][4] = {};
    float m0v = -1e30f, m1v = -1e30f, l0 = 0.f, l1 = 0.f;

    const float* Kg = g_K + (size_t)bh * N_ * 64;
    const float* Vg = qkv + (size_t)b * N_ * TC_ + 2 * C_ + h * 64;

    for (int t = 0; t < 16; ++t) {
        __syncthreads();
        #pragma unroll
        for (int i = 0; i < 4; ++i) {
            const int f = tid + i * 256;
            const int row = f >> 4, c4 = (f & 15) * 4;
            float4 kv = *(const float4*)&Kg[(size_t)(t * 64 + row) * 64 + c4];
            unsigned* kd = Ks + row * 68 + c4;
            kd[0]=f2tf(kv.x); kd[1]=f2tf(kv.y); kd[2]=f2tf(kv.z); kd[3]=f2tf(kv.w);
            float4 vv = *(const float4*)&Vg[(size_t)(t * 64 + row) * TC_ + c4];
            unsigned* vd = Vs + row * 72 + c4;
            vd[0]=f2tf(vv.x); vd[1]=f2tf(vv.y); vd[2]=f2tf(vv.z); vd[3]=f2tf(vv.w);
        }
        __syncthreads();

        // S = Q @ Ktile^T
        float s[8][4] = {};
        #pragma unroll
        for (int ks = 0; ks < 8; ++ks) {
            unsigned bf[8][2];
            #pragma unroll
            for (int nt = 0; nt < 8; ++nt) {
                bf[nt][0] = Ks[(nt * 8 + lr) * 68 + ks * 8 + lc];
                bf[nt][1] = Ks[(nt * 8 + lr) * 68 + ks * 8 + lc + 4];
            }
            #pragma unroll
            for (int nt = 0; nt < 8; ++nt)
                mma_tf32(s[nt], qf[ks], bf[nt]);
        }

        // online softmax (rows lr and lr+8; cols live in quad -> 2 shfls)
        float mt0 = -1e30f, mt1 = -1e30f;
        #pragma unroll
        for (int nt = 0; nt < 8; ++nt) {
            mt0 = fmaxf(mt0, fmaxf(s[nt][0], s[nt][1]));
            mt1 = fmaxf(mt1, fmaxf(s[nt][2], s[nt][3]));
        }
        mt0 = fmaxf(mt0, __shfl_xor_sync(0xffffffffu, mt0, 1));
        mt0 = fmaxf(mt0, __shfl_xor_sync(0xffffffffu, mt0, 2));
        mt1 = fmaxf(mt1, __shfl_xor_sync(0xffffffffu, mt1, 1));
        mt1 = fmaxf(mt1, __shfl_xor_sync(0xffffffffu, mt1, 2));
        const float mn0 = fmaxf(m0v, mt0), mn1 = fmaxf(m1v, mt1);
        const float cr0 = __expf(m0v - mn0), cr1 = __expf(m1v - mn1);
        float ps0 = 0.f, ps1 = 0.f;
        #pragma unroll
        for (int nt = 0; nt < 8; ++nt) {
            s[nt][0] = __expf(s[nt][0] - mn0);
            s[nt][1] = __expf(s[nt][1] - mn0);
            s[nt][2] = __expf(s[nt][2] - mn1);
            s[nt][3] = __expf(s[nt][3] - mn1);
            ps0 += s[nt][0] + s[nt][1];
            ps1 += s[nt][2] + s[nt][3];
        }
        ps0 += __shfl_xor_sync(0xffffffffu, ps0, 1);
        ps0 += __shfl_xor_sync(0xffffffffu, ps0, 2);
        ps1 += __shfl_xor_sync(0xffffffffu, ps1, 1);
        ps1 += __shfl_xor_sync(0xffffffffu, ps1, 2);
        l0 = l0 * cr0 + ps0; l1 = l1 * cr1 + ps1;
        m0v = mn0; m1v = mn1;
        #pragma unroll
        for (int nt = 0; nt < 8; ++nt) {
            o[nt][0] *= cr0; o[nt][1] *= cr0;
            o[nt][2] *= cr1; o[nt][3] *= cr1;
        }

        // O += P @ Vtile. Convert S(C-layout) -> A fragments via shuffles.
        #pragma unroll
        for (int ks = 0; ks < 8; ++ks) {
            const unsigned p0 = f2tf(s[ks][0]), p1 = f2tf(s[ks][1]);
            const unsigned p2 = f2tf(s[ks][2]), p3 = f2tf(s[ks][3]);
            const unsigned u0 = __shfl_sync(0xffffffffu, p0, qh);
            const unsigned u1 = __shfl_sync(0xffffffffu, p1, qh);
            const unsigned u2 = __shfl_sync(0xffffffffu, p0, qh + 2);
            const unsigned u3 = __shfl_sync(0xffffffffu, p1, qh + 2);
            const unsigned w0 = __shfl_sync(0xffffffffu, p2, qh);
            const unsigned w1 = __shfl_sync(0xffffffffu, p3, qh);
            const unsigned w2 = __shfl_sync(0xffffffffu, p2, qh + 2);
            const unsigned w3 = __shfl_sync(0xffffffffu, p3, qh + 2);
            unsigned pa[4];
            const bool odd = lc & 1;
            pa[0] = odd ? u1 : u0;    // (row,    k=lc)
            pa[1] = odd ? w1 : w0;    // (row+8,  k=lc)
            pa[2] = odd ? u3 : u2;    // (row,    k=lc+4)
            pa[3] = odd ? w3 : w2;    // (row+8,  k=lc+4)
            #pragma unroll
            for (int nt = 0; nt < 8; ++nt) {
                unsigned vb[2];
                vb[0] = Vs[(ks * 8 + lc) * 72 + nt * 8 + lr];
                vb[1] = Vs[(ks * 8 + lc + 4) * 72 + nt * 8 + lr];
                mma_tf32(o[nt], pa, vb);
            }
        }
    }

    const float il0 = 1.f / l0, il1 = 1.f / l1;
    float* dst = AO + ((size_t)(b * N_ + n0 + wid * 16 + lr)) * C_ + h * 64;
    #pragma unroll
    for (int nt = 0; nt < 8; ++nt) {
        const int col = nt * 8 + 2 * lc;
        float2 v0, v1;
        v0.x = o[nt][0] * il0; v0.y = o[nt][1] * il0;
        v1.x = o[nt][2] * il1; v1.y = o[nt][3] * il1;
        *(float2*)&dst[col] = v0;
        *(float2*)&dst[(size_t)8 * C_ + col] = v1;
    }
}

// ---------------------------------------------------------------------------
extern "C" void kernel_launch(void* const* d_in, const int* in_sizes, int n_in,
                              void* d_out, int out_size)
{
    const float* x      = (const float*)d_in[0];
    const float* qkv_w  = (const float*)d_in[1];
    const float* proj_w = (const float*)d_in[2];
    const float* proj_b = (const float*)d_in[3];
    float* out = (float*)d_out;

    float *qkv, *ao;
    cudaGetSymbolAddress((void**)&qkv, g_QKV);
    cudaGetSymbolAddress((void**)&ao,  g_AO);

    // 1) QKV projection: [8192,2304] = x @ qkv_w^T
    gemm_tf32<<<dim3(TC_ / 128, M_ / 128), 256>>>(x, qkv_w, nullptr, qkv, TC_, C_);
    // 2) per-head q/k standardization (+ softmax scale folded into Q)
    norm_qk_kernel<<<(2 * BH_ * N_) / 8, 256>>>(qkv);
    // 3) tensor-core flash attention
    attn_tf32<<<dim3(N_ / 128, BH_), 256>>>(qkv, ao);
    // 4) output projection + bias
    gemm_tf32<<<dim3(C_ / 128, M_ / 128), 256>>>(ao, proj_w, proj_b, out, C_, C_);
}

// round 4
// speedup vs baseline: 3.6286x; 1.0163x over previous
#include <cuda_runtime.h>
#include <cstdint>

#define B_  8
#define N_  1024
#define C_  768
#define H_  12
#define D_  64
#define BH_ (B_*H_)     // 96
#define M_  (B_*N_)     // 8192
#define TC_ (3*C_)      // 2304

// Scratch (device globals: allocation-free rule)
__device__ float    g_QKV[(size_t)M_ * TC_];      // [B*N, 3C]
__device__ float    g_Q  [(size_t)BH_ * N_ * D_]; // [B*H, N, D] normalized*scale
__device__ float    g_K  [(size_t)BH_ * N_ * D_]; // [B*H, N, D] normalized
__device__ float    g_AO [(size_t)M_ * C_];       // [B*N, C] attn out (tf32 bits)
__device__ unsigned g_Xc [(size_t)M_ * C_];       // x  converted to tf32 bits
__device__ unsigned g_Wq [(size_t)TC_ * C_];      // qkv_w tf32 bits
__device__ unsigned g_Wp [(size_t)C_ * C_];       // proj_w tf32 bits

__device__ __forceinline__ unsigned f2tf(float x) {
    unsigned r; asm("cvt.rna.tf32.f32 %0, %1;" : "=r"(r) : "f"(x)); return r;
}

__device__ __forceinline__ uint32_t smem_u32(const void* p) {
    uint32_t a;
    asm("{ .reg .u64 t; cvta.to.shared.u64 t, %1; cvt.u32.u64 %0, t; }" : "=r"(a) : "l"(p));
    return a;
}

__device__ __forceinline__ void cp_async16(uint32_t dst, const void* src) {
    asm volatile("cp.async.cg.shared.global [%0], [%1], 16;" :: "r"(dst), "l"(src) : "memory");
}
#define CP_COMMIT()  asm volatile("cp.async.commit_group;" ::: "memory")
#define CP_WAIT2()   asm volatile("cp.async.wait_group 2;" ::: "memory")

// D += A(16x8,row) * B(8x8,col) tf32, fp32 accum
__device__ __forceinline__ void mma_tf32(float* d, const unsigned* a, const unsigned* b) {
    asm volatile("mma.sync.aligned.m16n8k8.row.col.f32.tf32.tf32.f32 "
                 "{%0,%1,%2,%3}, {%4,%5,%6,%7}, {%8,%9}, {%0,%1,%2,%3};"
                 : "+f"(d[0]), "+f"(d[1]), "+f"(d[2]), "+f"(d[3])
                 : "r"(a[0]), "r"(a[1]), "r"(a[2]), "r"(a[3]),
                   "r"(b[0]), "r"(b[1]));
}

// ---------------------------------------------------------------------------
// elementwise fp32 -> tf32-bits conversion (n divisible by 1024)
// ---------------------------------------------------------------------------
__global__ void __launch_bounds__(256) cvt_tf32_kernel(
    const float* __restrict__ in, unsigned* __restrict__ out)
{
    const int i = (blockIdx.x * 256 + threadIdx.x) * 4;
    const float4 v = *(const float4*)(in + i);
    uint4 u;
    u.x = f2tf(v.x); u.y = f2tf(v.y); u.z = f2tf(v.z); u.w = f2tf(v.w);
    *(uint4*)(out + i) = u;
}

// ---------------------------------------------------------------------------
// tf32 mma.sync GEMM with cp.async 4-stage pipeline.
// C[M,N] = A[M,K] @ W[N,K]^T (+bias). A,W are pre-converted tf32 bits.
// 128x128 tile, BK=16, 8 warps (4m x 2n), warp 32x64, 2 CTAs/SM.
// ---------------------------------------------------------------------------
#define STG     4
#define ASTR    20                    // smem row stride (u32) -> conflict-free frags
#define STAGEU  (2 * 128 * ASTR)      // A+B per stage, in u32 (20KB)

__global__ void __launch_bounds__(256, 2) gemm_cp(
    const unsigned* __restrict__ A, const unsigned* __restrict__ W,
    const float* __restrict__ bias, float* __restrict__ Cout,
    int Nn, int K)
{
    extern __shared__ unsigned sm[];
    const uint32_t sbase = smem_u32(sm);

    const int tid  = threadIdx.x;
    const int wid  = tid >> 5, lane = tid & 31;
    const int lr   = lane >> 2, lc = lane & 3;
    const int wm   = (wid >> 1) * 32;
    const int wn   = (wid & 1) * 64;
    const int m0   = blockIdx.y * 128, n0 = blockIdx.x * 128;
    const int KT   = K >> 4;

    // load mapping: 2 uint4 per array per thread
    const int r0l = tid >> 1;                 // unused placeholder removed below
    (void)r0l;

    const unsigned* Ag = A + (size_t)m0 * K;
    const unsigned* Wg = W + (size_t)n0 * K;

    float acc[2][8][4] = {};

    // issue loads for stage s, k-tile kt
    auto issue = [&](int s, int kt) {
        const uint32_t abase = sbase + 4u * (s * STAGEU);
        const uint32_t bbase = abase + 4u * (128 * ASTR);
        #pragma unroll
        for (int j = 0; j < 2; ++j) {
            const int idx = tid + j * 256;          // 0..511
            const int r = idx >> 2, kq = (idx & 3) << 2;
            const size_t go = (size_t)r * K + kt * 16 + kq;
            const uint32_t so = 4u * (r * ASTR + kq);
            cp_async16(abase + so, Ag + go);
            cp_async16(bbase + so, Wg + go);
        }
        CP_COMMIT();
    };

    // prologue: stages 0..2
    issue(0, 0); issue(1, 1); issue(2, 2);

    for (int kt = 0; kt < KT; ++kt) {
        CP_WAIT2();
        __syncthreads();
        // refill the stage freed at iteration kt-1
        if (kt + 3 < KT) issue((kt + 3) & (STG - 1), kt + 3);
        else CP_COMMIT();

        const unsigned* Ab = sm + (kt & (STG - 1)) * STAGEU;
        const unsigned* Wb = Ab + 128 * ASTR;
        #pragma unroll
        for (int ks = 0; ks < 2; ++ks) {
            const int kb = ks * 8;
            unsigned af[2][4], bf[8][2];
            #pragma unroll
            for (int mt = 0; mt < 2; ++mt) {
                const int r = wm + mt * 16 + lr;
                af[mt][0] = Ab[r * ASTR + kb + lc];
                af[mt][1] = Ab[(r + 8) * ASTR + kb + lc];
                af[mt][2] = Ab[r * ASTR + kb + lc + 4];
                af[mt][3] = Ab[(r + 8) * ASTR + kb + lc + 4];
            }
            #pragma unroll
            for (int nt = 0; nt < 8; ++nt) {
                const int n = wn + nt * 8 + lr;
                bf[nt][0] = Wb[n * ASTR + kb + lc];
                bf[nt][1] = Wb[n * ASTR + kb + lc + 4];
            }
            #pragma unroll
            for (int mt = 0; mt < 2; ++mt)
                #pragma unroll
                for (int nt = 0; nt < 8; ++nt)
                    mma_tf32(acc[mt][nt], af[mt], bf[nt]);
        }
        __syncthreads();
    }

    #pragma unroll
    for (int mt = 0; mt < 2; ++mt)
        #pragma unroll
        for (int nt = 0; nt < 8; ++nt) {
            const int col = n0 + wn + nt * 8 + 2 * lc;
            float bx = 0.f, by = 0.f;
            if (bias) { bx = bias[col]; by = bias[col + 1]; }
            const int r = m0 + wm + mt * 16 + lr;
            float2 v0, v1;
            v0.x = acc[mt][nt][0] + bx; v0.y = acc[mt][nt][1] + by;
            v1.x = acc[mt][nt][2] + bx; v1.y = acc[mt][nt][3] + by;
            *(float2*)&Cout[(size_t)r * Nn + col] = v0;
            *(float2*)&Cout[(size_t)(r + 8) * Nn + col] = v1;
        }
}

// ---------------------------------------------------------------------------
// Per-head q/k standardization (ddof=1), one warp per row of 64.
// ---------------------------------------------------------------------------
__global__ void __launch_bounds__(256) norm_qk_kernel(const float* __restrict__ qkv)
{
    const int warp = threadIdx.x >> 5;
    const int lane = threadIdx.x & 31;
    const int row  = blockIdx.x * 8 + warp;
    const int isK  = row >= BH_ * N_;
    const int rid  = isK ? row - BH_ * N_ : row;
    const int bh = rid >> 10;
    const int n  = rid & 1023;
    const int b = bh / H_, h = bh % H_;

    const float* src = qkv + ((size_t)(b * N_ + n)) * TC_ + (isK ? C_ : 0) + h * D_;
    const float2 v = ((const float2*)src)[lane];

    float s  = v.x + v.y;
    float ss = v.x * v.x + v.y * v.y;
    #pragma unroll
    for (int off = 16; off; off >>= 1) {
        s  += __shfl_xor_sync(0xffffffffu, s,  off);
        ss += __shfl_xor_sync(0xffffffffu, ss, off);
    }
    const float mean = s * (1.0f / 64.0f);
    const float var  = (ss - 64.0f * mean * mean) * (1.0f / 63.0f);
    const float rs   = rsqrtf(var);
    const float sc   = isK ? rs : rs * 0.125f;   // fold SCALE into Q

    float2 o;
    o.x = (v.x - mean) * sc;
    o.y = (v.y - mean) * sc;
    float* dst = (isK ? g_K : g_Q) + (size_t)rid * 64;
    ((float2*)dst)[lane] = o;
}

// ---------------------------------------------------------------------------
// Flash attention via mma.sync tf32 (R2 version; epilogue writes tf32 bits).
// ---------------------------------------------------------------------------
__global__ void __launch_bounds__(256) attn_tf32(
    const float* __restrict__ qkv, float* __restrict__ AO)
{
    __shared__ unsigned Ks[64 * 68];
    __shared__ unsigned Vs[64 * 72];

    const int tid  = threadIdx.x;
    const int wid  = tid >> 5, lane = tid & 31;
    const int lr   = lane >> 2, lc = lane & 3;
    const int qh   = (lane & ~3) + (lc >> 1);
    const int bh   = blockIdx.y;
    const int n0   = blockIdx.x * 128;
    const int b = bh / H_, h = bh % H_;

    unsigned qf[8][4];
    {
        const float* Qg = g_Q + ((size_t)bh * N_ + n0 + wid * 16) * 64;
        #pragma unroll
        for (int ks = 0; ks < 8; ++ks) {
            qf[ks][0] = f2tf(Qg[lr * 64 + ks * 8 + lc]);
            qf[ks][1] = f2tf(Qg[(lr + 8) * 64 + ks * 8 + lc]);
            qf[ks][2] = f2tf(Qg[lr * 64 + ks * 8 + lc + 4]);
            qf[ks][3] = f2tf(Qg[(lr + 8) * 64 + ks * 8 + lc + 4]);
        }
    }

    float o[8][4] = {};
    float m0v = -1e30f, m1v = -1e30f, l0 = 0.f, l1 = 0.f;

    const float* Kg = g_K + (size_t)bh * N_ * 64;
    const float* Vg = qkv + (size_t)b * N_ * TC_ + 2 * C_ + h * 64;

    for (int t = 0; t < 16; ++t) {
        __syncthreads();
        #pragma unroll
        for (int i = 0; i < 4; ++i) {
            const int f = tid + i * 256;
            const int row = f >> 4, c4 = (f & 15) * 4;
            float4 kv = *(const float4*)&Kg[(size_t)(t * 64 + row) * 64 + c4];
            unsigned* kd = Ks + row * 68 + c4;
            kd[0]=f2tf(kv.x); kd[1]=f2tf(kv.y); kd[2]=f2tf(kv.z); kd[3]=f2tf(kv.w);
            float4 vv = *(const float4*)&Vg[(size_t)(t * 64 + row) * TC_ + c4];
            unsigned* vd = Vs + row * 72 + c4;
            vd[0]=f2tf(vv.x); vd[1]=f2tf(vv.y); vd[2]=f2tf(vv.z); vd[3]=f2tf(vv.w);
        }
        __syncthreads();

        float s[8][4] = {};
        #pragma unroll
        for (int ks = 0; ks < 8; ++ks) {
            unsigned bf[8][2];
            #pragma unroll
            for (int nt = 0; nt < 8; ++nt) {
                bf[nt][0] = Ks[(nt * 8 + lr) * 68 + ks * 8 + lc];
                bf[nt][1] = Ks[(nt * 8 + lr) * 68 + ks * 8 + lc + 4];
            }
            #pragma unroll
            for (int nt = 0; nt < 8; ++nt)
                mma_tf32(s[nt], qf[ks], bf[nt]);
        }

        float mt0 = -1e30f, mt1 = -1e30f;
        #pragma unroll
        for (int nt = 0; nt < 8; ++nt) {
            mt0 = fmaxf(mt0, fmaxf(s[nt][0], s[nt][1]));
            mt1 = fmaxf(mt1, fmaxf(s[nt][2], s[nt][3]));
        }
        mt0 = fmaxf(mt0, __shfl_xor_sync(0xffffffffu, mt0, 1));
        mt0 = fmaxf(mt0, __shfl_xor_sync(0xffffffffu, mt0, 2));
        mt1 = fmaxf(mt1, __shfl_xor_sync(0xffffffffu, mt1, 1));
        mt1 = fmaxf(mt1, __shfl_xor_sync(0xffffffffu, mt1, 2));
        const float mn0 = fmaxf(m0v, mt0), mn1 = fmaxf(m1v, mt1);
        const float cr0 = __expf(m0v - mn0), cr1 = __expf(m1v - mn1);
        float ps0 = 0.f, ps1 = 0.f;
        #pragma unroll
        for (int nt = 0; nt < 8; ++nt) {
            s[nt][0] = __expf(s[nt][0] - mn0);
            s[nt][1] = __expf(s[nt][1] - mn0);
            s[nt][2] = __expf(s[nt][2] - mn1);
            s[nt][3] = __expf(s[nt][3] - mn1);
            ps0 += s[nt][0] + s[nt][1];
            ps1 += s[nt][2] + s[nt][3];
        }
        ps0 += __shfl_xor_sync(0xffffffffu, ps0, 1);
        ps0 += __shfl_xor_sync(0xffffffffu, ps0, 2);
        ps1 += __shfl_xor_sync(0xffffffffu, ps1, 1);
        ps1 += __shfl_xor_sync(0xffffffffu, ps1, 2);
        l0 = l0 * cr0 + ps0; l1 = l1 * cr1 + ps1;
        m0v = mn0; m1v = mn1;
        #pragma unroll
        for (int nt = 0; nt < 8; ++nt) {
            o[nt][0] *= cr0; o[nt][1] *= cr0;
            o[nt][2] *= cr1; o[nt][3] *= cr1;
        }

        #pragma unroll
        for (int ks = 0; ks < 8; ++ks) {
            const unsigned p0 = f2tf(s[ks][0]), p1 = f2tf(s[ks][1]);
            const unsigned p2 = f2tf(s[ks][2]), p3 = f2tf(s[ks][3]);
            const unsigned u0 = __shfl_sync(0xffffffffu, p0, qh);
            const unsigned u1 = __shfl_sync(0xffffffffu, p1, qh);
            const unsigned u2 = __shfl_sync(0xffffffffu, p0, qh + 2);
            const unsigned u3 = __shfl_sync(0xffffffffu, p1, qh + 2);
            const unsigned w0 = __shfl_sync(0xffffffffu, p2, qh);
            const unsigned w1 = __shfl_sync(0xffffffffu, p3, qh);
            const unsigned w2 = __shfl_sync(0xffffffffu, p2, qh + 2);
            const unsigned w3 = __shfl_sync(0xffffffffu, p3, qh + 2);
            unsigned pa[4];
            const bool odd = lc & 1;
            pa[0] = odd ? u1 : u0;
            pa[1] = odd ? w1 : w0;
            pa[2] = odd ? u3 : u2;
            pa[3] = odd ? w3 : w2;
            #pragma unroll
            for (int nt = 0; nt < 8; ++nt) {
                unsigned vb[2];
                vb[0] = Vs[(ks * 8 + lc) * 72 + nt * 8 + lr];
                vb[1] = Vs[(ks * 8 + lc + 4) * 72 + nt * 8 + lr];
                mma_tf32(o[nt], pa, vb);
            }
        }
    }

    // epilogue: write tf32-converted bits so proj GEMM reads them raw
    const float il0 = 1.f / l0, il1 = 1.f / l1;
    float* dst = AO + ((size_t)(b * N_ + n0 + wid * 16 + lr)) * C_ + h * 64;
    #pragma unroll
    for (int nt = 0; nt < 8; ++nt) {
        const int col = nt * 8 + 2 * lc;
        float2 v0, v1;
        v0.x = __uint_as_float(f2tf(o[nt][0] * il0));
        v0.y = __uint_as_float(f2tf(o[nt][1] * il0));
        v1.x = __uint_as_float(f2tf(o[nt][2] * il1));
        v1.y = __uint_as_float(f2tf(o[nt][3] * il1));
        *(float2*)&dst[col] = v0;
        *(float2*)&dst[(size_t)8 * C_ + col] = v1;
    }
}

// ---------------------------------------------------------------------------
extern "C" void kernel_launch(void* const* d_in, const int* in_sizes, int n_in,
                              void* d_out, int out_size)
{
    const float* x      = (const float*)d_in[0];
    const float* qkv_w  = (const float*)d_in[1];
    const float* proj_w = (const float*)d_in[2];
    const float* proj_b = (const float*)d_in[3];
    float* out = (float*)d_out;

    float *qkv, *ao;
    unsigned *xc, *wq, *wp;
    cudaGetSymbolAddress((void**)&qkv, g_QKV);
    cudaGetSymbolAddress((void**)&ao,  g_AO);
    cudaGetSymbolAddress((void**)&xc,  g_Xc);
    cudaGetSymbolAddress((void**)&wq,  g_Wq);
    cudaGetSymbolAddress((void**)&wp,  g_Wp);

    const int GSM = STG * STAGEU * 4;   // 80 KB dynamic smem
    cudaFuncSetAttribute(gemm_cp, cudaFuncAttributeMaxDynamicSharedMemorySize, GSM);

    // 0) convert operands to tf32 bits
    cvt_tf32_kernel<<<(M_ * C_) / 1024, 256>>>(x, xc);
    cvt_tf32_kernel<<<(TC_ * C_) / 1024, 256>>>(qkv_w, wq);
    cvt_tf32_kernel<<<(C_ * C_) / 1024, 256>>>(proj_w, wp);
    // 1) QKV projection (tf32 mma.sync + cp.async pipeline)
    gemm_cp<<<dim3(TC_ / 128, M_ / 128), 256, GSM>>>(xc, wq, nullptr, qkv, TC_, C_);
    // 2) per-head q/k standardization (+ softmax scale folded into Q)
    norm_qk_kernel<<<(2 * BH_ * N_) / 8, 256>>>(qkv);
    // 3) tensor-core flash attention (writes tf32 bits into AO)
    attn_tf32<<<dim3(N_ / 128, BH_), 256>>>(qkv, ao);
    // 4) output projection + bias
    gemm_cp<<<dim3(C_ / 128, M_ / 128), 256, GSM>>>((const unsigned*)ao, wp, proj_b, out, C_, C_);
}

// round 5
// speedup vs baseline: 8.7897x; 2.4223x over previous
#include <cuda_runtime.h>
#include <cuda_fp16.h>
#include <cstdint>

#define B_  8
#define N_  1024
#define C_  768
#define H_  12
#define D_  64
#define BH_ (B_*H_)     // 96
#define M_  (B_*N_)     // 8192
#define TC_ (3*C_)      // 2304

// Scratch (device globals: allocation-free rule)
__device__ __half g_QKV[(size_t)M_ * TC_];      // [B*N, 3C] fp16
__device__ __half g_Q  [(size_t)BH_ * N_ * D_]; // [B*H, N, D] normalized*scale fp16
__device__ __half g_K  [(size_t)BH_ * N_ * D_]; // [B*H, N, D] normalized fp16
__device__ __half g_AO [(size_t)M_ * C_];       // [B*N, C] attn out fp16
__device__ __half g_Xh [(size_t)M_ * C_];       // x  fp16
__device__ __half g_Wq [(size_t)TC_ * C_];      // qkv_w fp16
__device__ __half g_Wp [(size_t)C_ * C_];       // proj_w fp16

// ---------------------------------------------------------------------------
// helpers
// ---------------------------------------------------------------------------
__device__ __forceinline__ uint32_t smem_u32(const void* p) {
    uint32_t a;
    asm("{ .reg .u64 t; cvta.to.shared.u64 t, %1; cvt.u32.u64 %0, t; }" : "=r"(a) : "l"(p));
    return a;
}

__device__ __forceinline__ void cp_async16(uint32_t dst, const void* src) {
    asm volatile("cp.async.cg.shared.global [%0], [%1], 16;" :: "r"(dst), "l"(src) : "memory");
}
#define CP_COMMIT()   asm volatile("cp.async.commit_group;" ::: "memory")
#define CP_WAIT(n)    asm volatile("cp.async.wait_group %0;" :: "n"(n) : "memory")

#define LDSM4(R0,R1,R2,R3,ADDR) \
    asm volatile("ldmatrix.sync.aligned.m8n8.x4.shared.b16 {%0,%1,%2,%3}, [%4];" \
        : "=r"(R0),"=r"(R1),"=r"(R2),"=r"(R3) : "r"(ADDR))
#define LDSM4T(R0,R1,R2,R3,ADDR) \
    asm volatile("ldmatrix.sync.aligned.m8n8.x4.trans.shared.b16 {%0,%1,%2,%3}, [%4];" \
        : "=r"(R0),"=r"(R1),"=r"(R2),"=r"(R3) : "r"(ADDR))

// D(16x8) += A(16x16) * B(16x8), fp16 in, fp32 accum
__device__ __forceinline__ void mma_f16(float* d, const unsigned* a, const unsigned* b) {
    asm volatile("mma.sync.aligned.m16n8k16.row.col.f32.f16.f16.f32 "
                 "{%0,%1,%2,%3}, {%4,%5,%6,%7}, {%8,%9}, {%0,%1,%2,%3};"
                 : "+f"(d[0]), "+f"(d[1]), "+f"(d[2]), "+f"(d[3])
                 : "r"(a[0]), "r"(a[1]), "r"(a[2]), "r"(a[3]),
                   "r"(b[0]), "r"(b[1]));
}

__device__ __forceinline__ unsigned pack_h2(float lo, float hi) {
    __half2 h = __floats2half2_rn(lo, hi);
    return *reinterpret_cast<unsigned*>(&h);
}

// ---------------------------------------------------------------------------
// fp32 -> fp16 conversion (count divisible by 1024)
// ---------------------------------------------------------------------------
__global__ void __launch_bounds__(256) cvt_h_kernel(
    const float* __restrict__ in, __half* __restrict__ out)
{
    const int i = (blockIdx.x * 256 + threadIdx.x) * 4;
    const float4 v = *(const float4*)(in + i);
    uint2 u;
    u.x = pack_h2(v.x, v.y);
    u.y = pack_h2(v.z, v.w);
    *(uint2*)(out + i) = u;
}

// ---------------------------------------------------------------------------
// fp16 HMMA GEMM: C[M,N] = A[M,K] @ W[N,K]^T (+bias), 128x128 tile, BK=32,
// cp.async 4 stages, ldmatrix fragments, 8 warps (4m x 2n), warp 32x64.
// OUT_HALF: write fp16 (no bias) else fp32 (+bias).
// ---------------------------------------------------------------------------
#define GKS     40                     // smem k-stride in halfs (80B rows)
#define GSTGB   (2 * 128 * GKS * 2)    // stage bytes (A+B) = 20480
#define GSMEMB  (4 * GSTGB)            // 81920

template<bool OUT_HALF>
__global__ void __launch_bounds__(256, 2) gemm_h(
    const __half* __restrict__ A, const __half* __restrict__ W,
    const float* __restrict__ bias, void* __restrict__ outp,
    int Nn, int K)
{
    extern __shared__ __half smh[];
    const uint32_t sbase = smem_u32(smh);

    const int tid = threadIdx.x;
    const int wid = tid >> 5, lane = tid & 31;
    const int lr = lane >> 2, lc = lane & 3;
    const int wm = (wid >> 1) * 32;
    const int wn = (wid & 1) * 64;
    const int m0 = blockIdx.y * 128, n0 = blockIdx.x * 128;
    const int KT = K >> 5;

    auto issue = [&](int s, int kt) {
        const uint32_t st = sbase + (uint32_t)s * GSTGB;
        #pragma unroll
        for (int j = 0; j < 4; ++j) {
            const int id = tid + j * 256;           // 0..1023
            const int arr = id >> 9;                // 0=A, 1=B
            const int idx = id & 511;
            const int r = idx >> 2, c = idx & 3;    // row, 16B chunk
            const __half* g = (arr ? W + (size_t)(n0 + r) * K
                                   : A + (size_t)(m0 + r) * K) + kt * 32 + c * 8;
            cp_async16(st + (uint32_t)arr * (128 * GKS * 2) + r * (GKS * 2) + c * 16, g);
        }
        CP_COMMIT();
    };

    float acc[2][8][4] = {};
    issue(0, 0); issue(1, 1); issue(2, 2);

    for (int kt = 0; kt < KT; ++kt) {
        CP_WAIT(2);
        __syncthreads();
        if (kt + 3 < KT) issue((kt + 3) & 3, kt + 3);
        else CP_COMMIT();

        const uint32_t Ab = sbase + (uint32_t)(kt & 3) * GSTGB;
        const uint32_t Bb = Ab + 128 * GKS * 2;
        #pragma unroll
        for (int ks = 0; ks < 2; ++ks) {
            unsigned af[2][4], bf[8][2];
            #pragma unroll
            for (int mt = 0; mt < 2; ++mt) {
                const uint32_t ad = Ab + (wm + mt * 16 + (lane & 15)) * (GKS * 2)
                                  + ks * 32 + (lane >> 4) * 16;
                LDSM4(af[mt][0], af[mt][1], af[mt][2], af[mt][3], ad);
            }
            #pragma unroll
            for (int ng = 0; ng < 4; ++ng) {
                const uint32_t bd = Bb + (wn + ng * 16 + ((lane >> 4) & 1) * 8 + (lane & 7)) * (GKS * 2)
                                  + ks * 32 + ((lane >> 3) & 1) * 16;
                LDSM4(bf[2*ng][0], bf[2*ng][1], bf[2*ng+1][0], bf[2*ng+1][1], bd);
            }
            #pragma unroll
            for (int mt = 0; mt < 2; ++mt)
                #pragma unroll
                for (int nt = 0; nt < 8; ++nt)
                    mma_f16(acc[mt][nt], af[mt], bf[nt]);
        }
        __syncthreads();
    }

    if (OUT_HALF) {
        __half* Co = (__half*)outp;
        #pragma unroll
        for (int mt = 0; mt < 2; ++mt)
            #pragma unroll
            for (int nt = 0; nt < 8; ++nt) {
                const int r = m0 + wm + mt * 16 + lr;
                const int col = n0 + wn + nt * 8 + 2 * lc;
                *(unsigned*)&Co[(size_t)r * Nn + col] =
                    pack_h2(acc[mt][nt][0], acc[mt][nt][1]);
                *(unsigned*)&Co[(size_t)(r + 8) * Nn + col] =
                    pack_h2(acc[mt][nt][2], acc[mt][nt][3]);
            }
    } else {
        float* Co = (float*)outp;
        #pragma unroll
        for (int mt = 0; mt < 2; ++mt)
            #pragma unroll
            for (int nt = 0; nt < 8; ++nt) {
                const int r = m0 + wm + mt * 16 + lr;
                const int col = n0 + wn + nt * 8 + 2 * lc;
                const float bx = bias[col], by = bias[col + 1];
                float2 v0, v1;
                v0.x = acc[mt][nt][0] + bx; v0.y = acc[mt][nt][1] + by;
                v1.x = acc[mt][nt][2] + bx; v1.y = acc[mt][nt][3] + by;
                *(float2*)&Co[(size_t)r * Nn + col] = v0;
                *(float2*)&Co[(size_t)(r + 8) * Nn + col] = v1;
            }
    }
}

// ---------------------------------------------------------------------------
// Per-head q/k standardization (ddof=1) on fp16 data, fp32 math.
// ---------------------------------------------------------------------------
__global__ void __launch_bounds__(256) norm_qk_kernel(const __half* __restrict__ qkv)
{
    const int warp = threadIdx.x >> 5;
    const int lane = threadIdx.x & 31;
    const int row  = blockIdx.x * 8 + warp;
    const int isK  = row >= BH_ * N_;
    const int rid  = isK ? row - BH_ * N_ : row;
    const int bh = rid >> 10;
    const int n  = rid & 1023;
    const int b = bh / H_, h = bh % H_;

    const __half* src = qkv + ((size_t)(b * N_ + n)) * TC_ + (isK ? C_ : 0) + h * D_;
    const float2 v = __half22float2(((const __half2*)src)[lane]);

    float s  = v.x + v.y;
    float ss = v.x * v.x + v.y * v.y;
    #pragma unroll
    for (int off = 16; off; off >>= 1) {
        s  += __shfl_xor_sync(0xffffffffu, s,  off);
        ss += __shfl_xor_sync(0xffffffffu, ss, off);
    }
    const float mean = s * (1.0f / 64.0f);
    const float var  = (ss - 64.0f * mean * mean) * (1.0f / 63.0f);
    const float rs   = rsqrtf(var);
    const float sc   = isK ? rs : rs * 0.125f;   // fold SCALE into Q

    __half* dst = (isK ? g_K : g_Q) + (size_t)rid * 64;
    ((__half2*)dst)[lane] = __floats2half2_rn((v.x - mean) * sc, (v.y - mean) * sc);
}

// ---------------------------------------------------------------------------
// Flash attention, fp16 HMMA. Block = 128 q-rows of one (b,h); 8 warps,
// warp owns 16 q-rows. Keys in tiles of 64, 2-stage cp.async. P reuses the
// S accumulator layout directly as A fragments (fp16 trick, no shuffles).
// ---------------------------------------------------------------------------
#define AQS   72                         // Q/K/V smem d-stride in halfs (144B)
#define AQB   (128 * AQS * 2)            // Q bytes  = 18432
#define AKB   (64 * AQS * 2)             // K/V tile bytes = 9216
#define ASMEMB (AQB + 4 * AKB)           // 55296

__global__ void __launch_bounds__(256, 2) attn_h(
    const __half* __restrict__ qkv, __half* __restrict__ AO)
{
    extern __shared__ __half smh[];
    const uint32_t Qb = smem_u32(smh);

    const int tid  = threadIdx.x;
    const int wid  = tid >> 5, lane = tid & 31;
    const int lr   = lane >> 2, lc = lane & 3;
    const int bh   = blockIdx.y;
    const int n0   = blockIdx.x * 128;
    const int b = bh / H_, h = bh % H_;

    const __half* Qg = g_Q + ((size_t)bh * N_ + n0) * 64;
    const __half* Kg = g_K + (size_t)bh * N_ * 64;
    const __half* Vg = qkv + (size_t)b * N_ * TC_ + 2 * C_ + h * 64;

    // group 0: Q tile (128 rows x 64 halfs = 1024 chunks)
    #pragma unroll
    for (int j = 0; j < 4; ++j) {
        const int id = tid + j * 256;
        const int r = id >> 3, c = id & 7;
        cp_async16(Qb + r * (AQS * 2) + c * 16, Qg + r * 64 + c * 8);
    }
    CP_COMMIT();

    auto issueKV = [&](int s, int t) {
        const uint32_t Kbs = Qb + AQB + (uint32_t)s * AKB;
        const uint32_t Vbs = Qb + AQB + 2 * AKB + (uint32_t)s * AKB;
        #pragma unroll
        for (int j = 0; j < 4; ++j) {
            const int id = tid + j * 256;
            const int arr = id >> 9;
            const int idx = id & 511;
            const int r = idx >> 3, c = idx & 7;
            if (arr == 0)
                cp_async16(Kbs + r * (AQS * 2) + c * 16, Kg + (size_t)(t * 64 + r) * 64 + c * 8);
            else
                cp_async16(Vbs + r * (AQS * 2) + c * 16, Vg + (size_t)(t * 64 + r) * TC_ + c * 8);
        }
        CP_COMMIT();
    };
    issueKV(0, 0);

    unsigned qf[4][4];
    float o[8][4] = {};
    float m0v = -1e30f, m1v = -1e30f, l0 = 0.f, l1 = 0.f;

    for (int t = 0; t < 16; ++t) {
        if (t + 1 < 16) { issueKV((t + 1) & 1, t + 1); CP_WAIT(1); }
        else            { CP_WAIT(0); }
        __syncthreads();

        if (t == 0) {   // Q fragments (group 0 drained by the wait above)
            #pragma unroll
            for (int ks = 0; ks < 4; ++ks) {
                const uint32_t ad = Qb + (wid * 16 + (lane & 15)) * (AQS * 2)
                                  + ks * 32 + (lane >> 4) * 16;
                LDSM4(qf[ks][0], qf[ks][1], qf[ks][2], qf[ks][3], ad);
            }
        }

        const uint32_t Kbs = Qb + AQB + (uint32_t)(t & 1) * AKB;
        const uint32_t Vbs = Qb + AQB + 2 * AKB + (uint32_t)(t & 1) * AKB;

        // S = Q @ Ktile^T  (m=16 q-rows, n=64 keys, k=64 d)
        float s[8][4] = {};
        #pragma unroll
        for (int ks = 0; ks < 4; ++ks) {
            unsigned bf[8][2];
            #pragma unroll
            for (int ng = 0; ng < 4; ++ng) {
                const uint32_t bd = Kbs + (ng * 16 + ((lane >> 4) & 1) * 8 + (lane & 7)) * (AQS * 2)
                                  + ks * 32 + ((lane >> 3) & 1) * 16;
                LDSM4(bf[2*ng][0], bf[2*ng][1], bf[2*ng+1][0], bf[2*ng+1][1], bd);
            }
            #pragma unroll
            for (int nt = 0; nt < 8; ++nt)
                mma_f16(s[nt], qf[ks], bf[nt]);
        }

        // online softmax (rows lr, lr+8; cols within quad -> 2 shfls)
        float mt0 = -1e30f, mt1 = -1e30f;
        #pragma unroll
        for (int nt = 0; nt < 8; ++nt) {
            mt0 = fmaxf(mt0, fmaxf(s[nt][0], s[nt][1]));
            mt1 = fmaxf(mt1, fmaxf(s[nt][2], s[nt][3]));
        }
        mt0 = fmaxf(mt0, __shfl_xor_sync(0xffffffffu, mt0, 1));
        mt0 = fmaxf(mt0, __shfl_xor_sync(0xffffffffu, mt0, 2));
        mt1 = fmaxf(mt1, __shfl_xor_sync(0xffffffffu, mt1, 1));
        mt1 = fmaxf(mt1, __shfl_xor_sync(0xffffffffu, mt1, 2));
        const float mn0 = fmaxf(m0v, mt0), mn1 = fmaxf(m1v, mt1);
        const float cr0 = __expf(m0v - mn0), cr1 = __expf(m1v - mn1);
        float ps0 = 0.f, ps1 = 0.f;
        #pragma unroll
        for (int nt = 0; nt < 8; ++nt) {
            s[nt][0] = __expf(s[nt][0] - mn0);
            s[nt][1] = __expf(s[nt][1] - mn0);
            s[nt][2] = __expf(s[nt][2] - mn1);
            s[nt][3] = __expf(s[nt][3] - mn1);
            ps0 += s[nt][0] + s[nt][1];
            ps1 += s[nt][2] + s[nt][3];
        }
        ps0 += __shfl_xor_sync(0xffffffffu, ps0, 1);
        ps0 += __shfl_xor_sync(0xffffffffu, ps0, 2);
        ps1 += __shfl_xor_sync(0xffffffffu, ps1, 1);
        ps1 += __shfl_xor_sync(0xffffffffu, ps1, 2);
        l0 = l0 * cr0 + ps0; l1 = l1 * cr1 + ps1;
        m0v = mn0; m1v = mn1;
        #pragma unroll
        for (int nt = 0; nt < 8; ++nt) {
            o[nt][0] *= cr0; o[nt][1] *= cr0;
            o[nt][2] *= cr1; o[nt][3] *= cr1;
        }

        // O += P @ Vtile  (k = 64 keys in 4 steps; P packs straight from S)
        #pragma unroll
        for (int ks = 0; ks < 4; ++ks) {
            unsigned pa[4];
            pa[0] = pack_h2(s[2*ks][0],   s[2*ks][1]);
            pa[1] = pack_h2(s[2*ks][2],   s[2*ks][3]);
            pa[2] = pack_h2(s[2*ks+1][0], s[2*ks+1][1]);
            pa[3] = pack_h2(s[2*ks+1][2], s[2*ks+1][3]);
            unsigned bf[8][2];
            #pragma unroll
            for (int dg = 0; dg < 4; ++dg) {
                const uint32_t vd = Vbs
                    + (ks * 16 + (lane & 7) + ((lane >> 3) & 1) * 8) * (AQS * 2)
                    + (dg * 16 + (lane >> 4) * 8) * 2;
                LDSM4T(bf[2*dg][0], bf[2*dg][1], bf[2*dg+1][0], bf[2*dg+1][1], vd);
            }
            #pragma unroll
            for (int nt = 0; nt < 8; ++nt)
                mma_f16(o[nt], pa, bf[nt]);
        }
        __syncthreads();
    }

    // epilogue: fp16 AO in [B,N,C]
    const float il0 = 1.f / l0, il1 = 1.f / l1;
    const int r0 = b * N_ + n0 + wid * 16 + lr;
    __half* dst = AO + (size_t)r0 * C_ + h * 64;
    #pragma unroll
    for (int nt = 0; nt < 8; ++nt) {
        const int col = nt * 8 + 2 * lc;
        *(unsigned*)&dst[col] = pack_h2(o[nt][0] * il0, o[nt][1] * il0);
        *(unsigned*)&dst[(size_t)8 * C_ + col] = pack_h2(o[nt][2] * il1, o[nt][3] * il1);
    }
}

// ---------------------------------------------------------------------------
extern "C" void kernel_launch(void* const* d_in, const int* in_sizes, int n_in,
                              void* d_out, int out_size)
{
    const float* x      = (const float*)d_in[0];
    const float* qkv_w  = (const float*)d_in[1];
    const float* proj_w = (const float*)d_in[2];
    const float* proj_b = (const float*)d_in[3];
    float* out = (float*)d_out;

    __half *qkv, *ao, *xh, *wq, *wp;
    cudaGetSymbolAddress((void**)&qkv, g_QKV);
    cudaGetSymbolAddress((void**)&ao,  g_AO);
    cudaGetSymbolAddress((void**)&xh,  g_Xh);
    cudaGetSymbolAddress((void**)&wq,  g_Wq);
    cudaGetSymbolAddress((void**)&wp,  g_Wp);

    cudaFuncSetAttribute(gemm_h<true>,  cudaFuncAttributeMaxDynamicSharedMemorySize, GSMEMB);
    cudaFuncSetAttribute(gemm_h<false>, cudaFuncAttributeMaxDynamicSharedMemorySize, GSMEMB);
    cudaFuncSetAttribute(attn_h,        cudaFuncAttributeMaxDynamicSharedMemorySize, ASMEMB);

    // 0) fp32 -> fp16 operand conversion
    cvt_h_kernel<<<(M_ * C_) / 1024, 256>>>(x, xh);
    cvt_h_kernel<<<(TC_ * C_) / 1024, 256>>>(qkv_w, wq);
    cvt_h_kernel<<<(C_ * C_) / 1024, 256>>>(proj_w, wp);
    // 1) QKV projection -> fp16 [B*N, 3C]
    gemm_h<true><<<dim3(TC_ / 128, M_ / 128), 256, GSMEMB>>>(xh, wq, nullptr, qkv, TC_, C_);
    // 2) per-head q/k standardization (+ softmax scale folded into Q)
    norm_qk_kernel<<<(2 * BH_ * N_) / 8, 256>>>(qkv);
    // 3) fp16 flash attention -> fp16 AO
    attn_h<<<dim3(N_ / 128, BH_), 256, ASMEMB>>>(qkv, ao);
    // 4) output projection + bias -> fp32
    gemm_h<false><<<dim3(C_ / 128, M_ / 128), 256, GSMEMB>>>(ao, wp, proj_b, out, C_, C_);
}

// round 6
// speedup vs baseline: 9.5508x; 1.0866x over previous
#include <cuda_runtime.h>
#include <cuda_fp16.h>
#include <cstdint>

#define B_  8
#define N_  1024
#define C_  768
#define H_  12
#define D_  64
#define BH_ (B_*H_)     // 96
#define M_  (B_*N_)     // 8192
#define TC_ (3*C_)      // 2304

// Scratch (device globals: allocation-free rule)
__device__ __half g_Q  [(size_t)BH_ * N_ * D_]; // [B*H, N, D] normalized*scale
__device__ __half g_K  [(size_t)BH_ * N_ * D_]; // [B*H, N, D] normalized
__device__ __half g_V  [(size_t)BH_ * N_ * D_]; // [B*H, N, D]
__device__ __half g_AO [(size_t)M_ * C_];       // [B*N, C] attn out fp16
__device__ __half g_Xh [(size_t)M_ * C_];       // x fp16
__device__ __half g_Wq [(size_t)TC_ * C_];      // qkv_w fp16
__device__ __half g_Wp [(size_t)C_ * C_];       // proj_w fp16

// ---------------------------------------------------------------------------
// helpers
// ---------------------------------------------------------------------------
__device__ __forceinline__ uint32_t smem_u32(const void* p) {
    uint32_t a;
    asm("{ .reg .u64 t; cvta.to.shared.u64 t, %1; cvt.u32.u64 %0, t; }" : "=r"(a) : "l"(p));
    return a;
}

__device__ __forceinline__ void cp_async16(uint32_t dst, const void* src) {
    asm volatile("cp.async.cg.shared.global [%0], [%1], 16;" :: "r"(dst), "l"(src) : "memory");
}
#define CP_COMMIT()   asm volatile("cp.async.commit_group;" ::: "memory")
#define CP_WAIT(n)    asm volatile("cp.async.wait_group %0;" :: "n"(n) : "memory")

#define LDSM4(R0,R1,R2,R3,ADDR) \
    asm volatile("ldmatrix.sync.aligned.m8n8.x4.shared.b16 {%0,%1,%2,%3}, [%4];" \
        : "=r"(R0),"=r"(R1),"=r"(R2),"=r"(R3) : "r"(ADDR))
#define LDSM4T(R0,R1,R2,R3,ADDR) \
    asm volatile("ldmatrix.sync.aligned.m8n8.x4.trans.shared.b16 {%0,%1,%2,%3}, [%4];" \
        : "=r"(R0),"=r"(R1),"=r"(R2),"=r"(R3) : "r"(ADDR))

// D(16x8) += A(16x16) * B(16x8), fp16 in, fp32 accum
__device__ __forceinline__ void mma_f16(float* d, const unsigned* a, const unsigned* b) {
    asm volatile("mma.sync.aligned.m16n8k16.row.col.f32.f16.f16.f32 "
                 "{%0,%1,%2,%3}, {%4,%5,%6,%7}, {%8,%9}, {%0,%1,%2,%3};"
                 : "+f"(d[0]), "+f"(d[1]), "+f"(d[2]), "+f"(d[3])
                 : "r"(a[0]), "r"(a[1]), "r"(a[2]), "r"(a[3]),
                   "r"(b[0]), "r"(b[1]));
}

__device__ __forceinline__ unsigned pack_h2(float lo, float hi) {
    __half2 h = __floats2half2_rn(lo, hi);
    return *reinterpret_cast<unsigned*>(&h);
}

// ---------------------------------------------------------------------------
// fp32 -> fp16 conversion (count divisible by 1024)
// ---------------------------------------------------------------------------
__global__ void __launch_bounds__(256) cvt_h_kernel(
    const float* __restrict__ in, __half* __restrict__ out)
{
    const int i = (blockIdx.x * 256 + threadIdx.x) * 4;
    const float4 v = *(const float4*)(in + i);
    uint2 u;
    u.x = pack_h2(v.x, v.y);
    u.y = pack_h2(v.z, v.w);
    *(uint2*)(out + i) = u;
}

// ---------------------------------------------------------------------------
// fp16 HMMA GEMM: 128x128 tile, BK=32, 5-stage cp.async ring (ONE barrier per
// k-tile), ldmatrix fragments, 8 warps (4m x 2n), warp tile 32x64.
// MODE 0: QKV projection -> fused per-head q/k standardization, writes fp16
//         g_Q (scaled), g_K, g_V in [B*H, N, D] layout.
// MODE 1: proj GEMM -> fp32 out + bias.
// ---------------------------------------------------------------------------
#define GKS     40                     // smem k-stride in halfs (80B rows)
#define GSTG    5
#define GSTGB   (2 * 128 * GKS * 2)    // stage bytes (A+B) = 20480
#define GSMEMB  (GSTG * GSTGB)         // 102400

template<int MODE>
__global__ void __launch_bounds__(256, 2) gemm_h(
    const __half* __restrict__ A, const __half* __restrict__ W,
    const float* __restrict__ bias, float* __restrict__ outF,
    __half* __restrict__ Qo, __half* __restrict__ Ko, __half* __restrict__ Vo,
    int Nn, int K)
{
    extern __shared__ __half smh[];
    const uint32_t sbase = smem_u32(smh);

    const int tid = threadIdx.x;
    const int wid = tid >> 5, lane = tid & 31;
    const int lr = lane >> 2, lc = lane & 3;
    const int wm = (wid >> 1) * 32;
    const int wn = (wid & 1) * 64;
    const int m0 = blockIdx.y * 128, n0 = blockIdx.x * 128;
    const int KT = K >> 5;

    auto issue = [&](int s, int kt) {
        const uint32_t st = sbase + (uint32_t)s * GSTGB;
        #pragma unroll
        for (int j = 0; j < 4; ++j) {
            const int id = tid + j * 256;           // 0..1023
            const int arr = id >> 9;                // 0=A, 1=B
            const int idx = id & 511;
            const int r = idx >> 2, c = idx & 3;    // row, 16B chunk
            const __half* g = (arr ? W + (size_t)(n0 + r) * K
                                   : A + (size_t)(m0 + r) * K) + kt * 32 + c * 8;
            cp_async16(st + (uint32_t)arr * (128 * GKS * 2) + r * (GKS * 2) + c * 16, g);
        }
        CP_COMMIT();
    };

    float acc[2][8][4] = {};
    issue(0, 0); issue(1, 1); issue(2, 2); issue(3, 3);

    int sr = 0, sw = 4;
    for (int kt = 0; kt < KT; ++kt) {
        CP_WAIT(3);
        __syncthreads();
        if (kt + 4 < KT) issue(sw, kt + 4);
        else CP_COMMIT();
        if (++sw == GSTG) sw = 0;

        const uint32_t Ab = sbase + (uint32_t)sr * GSTGB;
        const uint32_t Bb = Ab + 128 * GKS * 2;
        if (++sr == GSTG) sr = 0;
        #pragma unroll
        for (int ks = 0; ks < 2; ++ks) {
            unsigned af[2][4], bf[8][2];
            #pragma unroll
            for (int mt = 0; mt < 2; ++mt) {
                const uint32_t ad = Ab + (wm + mt * 16 + (lane & 15)) * (GKS * 2)
                                  + ks * 32 + (lane >> 4) * 16;
                LDSM4(af[mt][0], af[mt][1], af[mt][2], af[mt][3], ad);
            }
            #pragma unroll
            for (int ng = 0; ng < 4; ++ng) {
                const uint32_t bd = Bb + (wn + ng * 16 + ((lane >> 4) & 1) * 8 + (lane & 7)) * (GKS * 2)
                                  + ks * 32 + ((lane >> 3) & 1) * 16;
                LDSM4(bf[2*ng][0], bf[2*ng][1], bf[2*ng+1][0], bf[2*ng+1][1], bd);
            }
            #pragma unroll
            for (int mt = 0; mt < 2; ++mt)
                #pragma unroll
                for (int nt = 0; nt < 8; ++nt)
                    mma_f16(acc[mt][nt], af[mt], bf[nt]);
        }
    }

    if (MODE == 0) {
        // QKV epilogue with fused q/k standardization (ddof=1).
        // Warp tile = 32 rows x 64 cols = one head slice.
        const int gc   = n0 + wn;                       // multiple of 64
        const int type = gc < C_ ? 0 : (gc < 2 * C_ ? 1 : 2);
        const int head = (gc - type * C_) >> 6;
        __half* basep  = type == 0 ? Qo : (type == 1 ? Ko : Vo);
        #pragma unroll
        for (int mt = 0; mt < 2; ++mt)
            #pragma unroll
            for (int rh = 0; rh < 2; ++rh) {
                const int r = m0 + wm + mt * 16 + rh * 8 + lr;
                const int b = r >> 10, n = r & 1023;
                __half* dst = basep + ((size_t)(b * H_ + head) * N_ + n) * 64;
                if (type < 2) {
                    float s = 0.f, ss = 0.f;
                    #pragma unroll
                    for (int nt = 0; nt < 8; ++nt) {
                        const float v0 = acc[mt][nt][2*rh], v1 = acc[mt][nt][2*rh+1];
                        s  += v0 + v1;
                        ss += v0 * v0 + v1 * v1;
                    }
                    s  += __shfl_xor_sync(0xffffffffu, s, 1);
                    s  += __shfl_xor_sync(0xffffffffu, s, 2);
                    ss += __shfl_xor_sync(0xffffffffu, ss, 1);
                    ss += __shfl_xor_sync(0xffffffffu, ss, 2);
                    const float mean = s * (1.0f / 64.0f);
                    const float var  = (ss - 64.0f * mean * mean) * (1.0f / 63.0f);
                    const float sc   = rsqrtf(var) * (type == 0 ? 0.125f : 1.0f);
                    #pragma unroll
                    for (int nt = 0; nt < 8; ++nt)
                        *(unsigned*)&dst[nt * 8 + 2 * lc] =
                            pack_h2((acc[mt][nt][2*rh]   - mean) * sc,
                                    (acc[mt][nt][2*rh+1] - mean) * sc);
                } else {
                    #pragma unroll
                    for (int nt = 0; nt < 8; ++nt)
                        *(unsigned*)&dst[nt * 8 + 2 * lc] =
                            pack_h2(acc[mt][nt][2*rh], acc[mt][nt][2*rh+1]);
                }
            }
    } else {
        #pragma unroll
        for (int mt = 0; mt < 2; ++mt)
            #pragma unroll
            for (int nt = 0; nt < 8; ++nt) {
                const int r = m0 + wm + mt * 16 + lr;
                const int col = n0 + wn + nt * 8 + 2 * lc;
                const float bx = bias[col], by = bias[col + 1];
                float2 v0, v1;
                v0.x = acc[mt][nt][0] + bx; v0.y = acc[mt][nt][1] + by;
                v1.x = acc[mt][nt][2] + bx; v1.y = acc[mt][nt][3] + by;
                *(float2*)&outF[(size_t)r * Nn + col] = v0;
                *(float2*)&outF[(size_t)(r + 8) * Nn + col] = v1;
            }
    }
}

// ---------------------------------------------------------------------------
// Flash attention, fp16 HMMA. Block = 128 q-rows of one (b,h); 8 warps, warp
// owns 16 q-rows. K/V tiles of 64 keys, 3-stage cp.async ring, ONE barrier
// per tile. P reuses S accumulator layout directly as A fragments.
// ---------------------------------------------------------------------------
#define AQS   72                         // Q/K/V smem d-stride in halfs (144B)
#define AQB   (128 * AQS * 2)            // Q bytes = 18432
#define AKB   (64 * AQS * 2)             // one K or V tile = 9216
#define AKVS  (2 * AKB)                  // KV stage bytes = 18432
#define ASMEMB (AQB + 3 * AKVS)          // 73728

__global__ void __launch_bounds__(256, 2) attn_h(__half* __restrict__ AO)
{
    extern __shared__ __half smh[];
    const uint32_t Qb = smem_u32(smh);

    const int tid  = threadIdx.x;
    const int wid  = tid >> 5, lane = tid & 31;
    const int lr   = lane >> 2, lc = lane & 3;
    const int bh   = blockIdx.y;
    const int n0   = blockIdx.x * 128;
    const int b = bh / H_, h = bh % H_;

    const __half* Qg = g_Q + ((size_t)bh * N_ + n0) * 64;
    const __half* Kg = g_K + (size_t)bh * N_ * 64;
    const __half* Vg = g_V + (size_t)bh * N_ * 64;

    // group 0: Q tile (128 rows x 64 halfs = 1024 16B chunks)
    #pragma unroll
    for (int j = 0; j < 4; ++j) {
        const int id = tid + j * 256;
        const int r = id >> 3, c = id & 7;
        cp_async16(Qb + r * (AQS * 2) + c * 16, Qg + r * 64 + c * 8);
    }
    CP_COMMIT();

    auto issueKV = [&](int s, int t) {
        const uint32_t Kbs = Qb + AQB + (uint32_t)s * AKVS;
        const uint32_t Vbs = Kbs + AKB;
        #pragma unroll
        for (int j = 0; j < 4; ++j) {
            const int id = tid + j * 256;
            const int arr = id >> 9;
            const int idx = id & 511;
            const int r = idx >> 3, c = idx & 7;
            const __half* g = (arr ? Vg : Kg) + (size_t)(t * 64 + r) * 64 + c * 8;
            cp_async16((arr ? Vbs : Kbs) + r * (AQS * 2) + c * 16, g);
        }
        CP_COMMIT();
    };
    issueKV(0, 0); issueKV(1, 1);

    unsigned qf[4][4];
    float o[8][4] = {};
    float m0v = -1e30f, m1v = -1e30f, l0 = 0.f, l1 = 0.f;

    int sr = 0, sw = 2;
    for (int t = 0; t < 16; ++t) {
        CP_WAIT(1);
        __syncthreads();
        if (t + 2 < 16) issueKV(sw, t + 2);
        else CP_COMMIT();
        if (++sw == 3) sw = 0;

        if (t == 0) {   // Q fragments (group 0 drained by the wait above)
            #pragma unroll
            for (int ks = 0; ks < 4; ++ks) {
                const uint32_t ad = Qb + (wid * 16 + (lane & 15)) * (AQS * 2)
                                  + ks * 32 + (lane >> 4) * 16;
                LDSM4(qf[ks][0], qf[ks][1], qf[ks][2], qf[ks][3], ad);
            }
        }

        const uint32_t Kbs = Qb + AQB + (uint32_t)sr * AKVS;
        const uint32_t Vbs = Kbs + AKB;
        if (++sr == 3) sr = 0;

        // S = Q @ Ktile^T  (m=16 q-rows, n=64 keys, k=64 d)
        float s[8][4] = {};
        #pragma unroll
        for (int ks = 0; ks < 4; ++ks) {
            unsigned bf[8][2];
            #pragma unroll
            for (int ng = 0; ng < 4; ++ng) {
                const uint32_t bd = Kbs + (ng * 16 + ((lane >> 4) & 1) * 8 + (lane & 7)) * (AQS * 2)
                                  + ks * 32 + ((lane >> 3) & 1) * 16;
                LDSM4(bf[2*ng][0], bf[2*ng][1], bf[2*ng+1][0], bf[2*ng+1][1], bd);
            }
            #pragma unroll
            for (int nt = 0; nt < 8; ++nt)
                mma_f16(s[nt], qf[ks], bf[nt]);
        }

        // online softmax (rows lr, lr+8; cols within quad -> 2 shfls)
        float mt0 = -1e30f, mt1 = -1e30f;
        #pragma unroll
        for (int nt = 0; nt < 8; ++nt) {
            mt0 = fmaxf(mt0, fmaxf(s[nt][0], s[nt][1]));
            mt1 = fmaxf(mt1, fmaxf(s[nt][2], s[nt][3]));
        }
        mt0 = fmaxf(mt0, __shfl_xor_sync(0xffffffffu, mt0, 1));
        mt0 = fmaxf(mt0, __shfl_xor_sync(0xffffffffu, mt0, 2));
        mt1 = fmaxf(mt1, __shfl_xor_sync(0xffffffffu, mt1, 1));
        mt1 = fmaxf(mt1, __shfl_xor_sync(0xffffffffu, mt1, 2));
        const float mn0 = fmaxf(m0v, mt0), mn1 = fmaxf(m1v, mt1);
        const float cr0 = __expf(m0v - mn0), cr1 = __expf(m1v - mn1);
        float ps0 = 0.f, ps1 = 0.f;
        #pragma unroll
        for (int nt = 0; nt < 8; ++nt) {
            s[nt][0] = __expf(s[nt][0] - mn0);
            s[nt][1] = __expf(s[nt][1] - mn0);
            s[nt][2] = __expf(s[nt][2] - mn1);
            s[nt][3] = __expf(s[nt][3] - mn1);
            ps0 += s[nt][0] + s[nt][1];
            ps1 += s[nt][2] + s[nt][3];
        }
        ps0 += __shfl_xor_sync(0xffffffffu, ps0, 1);
        ps0 += __shfl_xor_sync(0xffffffffu, ps0, 2);
        ps1 += __shfl_xor_sync(0xffffffffu, ps1, 1);
        ps1 += __shfl_xor_sync(0xffffffffu, ps1, 2);
        l0 = l0 * cr0 + ps0; l1 = l1 * cr1 + ps1;
        m0v = mn0; m1v = mn1;
        #pragma unroll
        for (int nt = 0; nt < 8; ++nt) {
            o[nt][0] *= cr0; o[nt][1] *= cr0;
            o[nt][2] *= cr1; o[nt][3] *= cr1;
        }

        // O += P @ Vtile  (k = 64 keys in 4 steps; P packs straight from S)
        #pragma unroll
        for (int ks = 0; ks < 4; ++ks) {
            unsigned pa[4];
            pa[0] = pack_h2(s[2*ks][0],   s[2*ks][1]);
            pa[1] = pack_h2(s[2*ks][2],   s[2*ks][3]);
            pa[2] = pack_h2(s[2*ks+1][0], s[2*ks+1][1]);
            pa[3] = pack_h2(s[2*ks+1][2], s[2*ks+1][3]);
            unsigned bf[8][2];
            #pragma unroll
            for (int dg = 0; dg < 4; ++dg) {
                const uint32_t vd = Vbs
                    + (ks * 16 + (lane & 7) + ((lane >> 3) & 1) * 8) * (AQS * 2)
                    + (dg * 16 + (lane >> 4) * 8) * 2;
                LDSM4T(bf[2*dg][0], bf[2*dg][1], bf[2*dg+1][0], bf[2*dg+1][1], vd);
            }
            #pragma unroll
            for (int nt = 0; nt < 8; ++nt)
                mma_f16(o[nt], pa, bf[nt]);
        }
    }

    // epilogue: fp16 AO in [B,N,C]
    const float il0 = 1.f / l0, il1 = 1.f / l1;
    const int r0 = b * N_ + n0 + wid * 16 + lr;
    __half* dst = AO + (size_t)r0 * C_ + h * 64;
    #pragma unroll
    for (int nt = 0; nt < 8; ++nt) {
        const int col = nt * 8 + 2 * lc;
        *(unsigned*)&dst[col] = pack_h2(o[nt][0] * il0, o[nt][1] * il0);
        *(unsigned*)&dst[(size_t)8 * C_ + col] = pack_h2(o[nt][2] * il1, o[nt][3] * il1);
    }
}

// ---------------------------------------------------------------------------
extern "C" void kernel_launch(void* const* d_in, const int* in_sizes, int n_in,
                              void* d_out, int out_size)
{
    const float* x      = (const float*)d_in[0];
    const float* qkv_w  = (const float*)d_in[1];
    const float* proj_w = (const float*)d_in[2];
    const float* proj_b = (const float*)d_in[3];
    float* out = (float*)d_out;

    __half *q, *k, *v, *ao, *xh, *wq, *wp;
    cudaGetSymbolAddress((void**)&q,   g_Q);
    cudaGetSymbolAddress((void**)&k,   g_K);
    cudaGetSymbolAddress((void**)&v,   g_V);
    cudaGetSymbolAddress((void**)&ao,  g_AO);
    cudaGetSymbolAddress((void**)&xh,  g_Xh);
    cudaGetSymbolAddress((void**)&wq,  g_Wq);
    cudaGetSymbolAddress((void**)&wp,  g_Wp);

    cudaFuncSetAttribute(gemm_h<0>, cudaFuncAttributeMaxDynamicSharedMemorySize, GSMEMB);
    cudaFuncSetAttribute(gemm_h<1>, cudaFuncAttributeMaxDynamicSharedMemorySize, GSMEMB);
    cudaFuncSetAttribute(attn_h,    cudaFuncAttributeMaxDynamicSharedMemorySize, ASMEMB);

    // 0) fp32 -> fp16 operand conversion
    cvt_h_kernel<<<(M_ * C_) / 1024, 256>>>(x, xh);
    cvt_h_kernel<<<(TC_ * C_) / 1024, 256>>>(qkv_w, wq);
    cvt_h_kernel<<<(C_ * C_) / 1024, 256>>>(proj_w, wp);
    // 1) QKV projection + fused q/k standardization -> g_Q, g_K, g_V
    gemm_h<0><<<dim3(TC_ / 128, M_ / 128), 256, GSMEMB>>>(
        xh, wq, nullptr, nullptr, q, k, v, TC_, C_);
    // 2) fp16 flash attention -> fp16 AO
    attn_h<<<dim3(N_ / 128, BH_), 256, ASMEMB>>>(ao);
    // 3) output projection + bias -> fp32
    gemm_h<1><<<dim3(C_ / 128, M_ / 128), 256, GSMEMB>>>(
        ao, wp, proj_b, out, nullptr, nullptr, nullptr, C_, C_);
}